// round 5
// baseline (speedup 1.0000x reference)
#include <cuda_runtime.h>

// Residual VQ (L=8, G=2, K=1024, D=256), B=16, T=4096, N=B*T=65536.
// Bit-replicates CPU-JAX (XLA/Eigen) fp32 semantics. GEMM uses packed
// fma.rn.f32x2 over TOKEN pairs (a-operand loads natively as 64-bit pairs
// from [d][t] SMEM; each lane is an independent rn-rounded fp32 FMA chain,
// bit-identical to scalar FFMA — verified in round 4).
// Outputs: [0,33554432) qout [B,C,T]; [33554432] loss; [+1,+1048576) indices [L,G,N]

#define LL 8
#define GG 2
#define KK 1024
#define DD 256
#define TT 4096
#define NTOK 65536ull
#define TILE 64
#define NTH 256
#define EPITCH 132

#define QOUT_ELEMS 33554432ull
#define LOSS_OFF   33554432ull
#define IDX_OFF    33554433ull

__device__ float  g_e2[LL * GG * KK];
__device__ double g_loss[2048];

typedef unsigned long long u64t;

__device__ __forceinline__ u64t dup2(float v) {
    u64t r;
    asm("mov.b64 %0, {%1, %1};" : "=l"(r) : "f"(v));
    return r;
}
__device__ __forceinline__ void fma2(u64t& d, u64t a, u64t b) {
    asm("fma.rn.f32x2 %0, %1, %2, %3;" : "=l"(d) : "l"(a), "l"(b), "l"(d));
}
__device__ __forceinline__ void unpack2(u64t v, float& lo, float& hi) {
    asm("mov.b64 {%0, %1}, %2;" : "=f"(lo), "=f"(hi) : "l"(v));
}

// ---------------------------------------------------------------- ||e||^2 (exact ref rounding)
__global__ void e2_kernel(const float* __restrict__ cb) {
    int c = blockIdx.x * blockDim.x + threadIdx.x;
    if (c >= LL * GG * KK) return;
    const float* e = cb + (size_t)c * DD;
    float s = 0.0f;
    for (int d = 0; d < DD; ++d) {
        float v = e[d];
        s = __fadd_rn(s, __fmul_rn(v, v));
    }
    g_e2[c] = s;
}

// ---------------------------------------------------------------- main
__global__ void __launch_bounds__(NTH, 2)
rvq_kernel(const float* __restrict__ xin, const float* __restrict__ cb,
           float* __restrict__ dout, unsigned long long out_size) {
    extern __shared__ float sm[];
    float* X    = sm;                          // [256][64] residual, [d][t]
    float* E    = X + DD * TILE;               // [16][EPITCH] transposed e chunk
    float* E2s  = E + 16 * EPITCH;             // [128] ||e||^2 of current code block
    float* SCRV = E2s + 128;                   // [64][32] per-(token,tn) local min
    int*   SCRI = (int*)(SCRV + TILE * 32);    // [64][32]
    float* RUNV = (float*)(SCRI + TILE * 32);  // [64]
    int*   RUNI = (int*)(RUNV + TILE);         // [64]
    float* Asm  = (float*)(RUNI + TILE);       // [64] ||x||^2 per token

    const int tid  = threadIdx.x;
    const int g    = blockIdx.y;
    const int tile = blockIdx.x;
    const int b    = tile >> 6;
    const int t0   = (tile & 63) << 6;
    const float* xb = xin + ((size_t)b * (GG * DD) + (size_t)g * DD) * TT + t0;

    for (int i = tid; i < DD * TILE; i += NTH) {
        int d = i >> 6, t = i & 63;
        X[i] = xb[(size_t)d * TT + t];
    }
    __syncthreads();

    const int tm = tid & 7;    // tokens 8*tm .. 8*tm+7 (4 f32x2 pairs)
    const int tn = tid >> 3;   // codes  4*tn .. 4*tn+3
    const int q  = tid & 3;    // d-quad for chunk loads
    const int kc = tid >> 2;   // code row for chunk loads (0..63)

    double lacc = 0.0;

    for (int l = 0; l < LL; ++l) {
        const float* cbl = cb + ((size_t)(l * GG + g)) * KK * DD;

        // a_n = sequential sum of fl(x^2), d ascending (ref reduce order)
        if (tid < TILE) {
            float s = 0.0f;
            const float* xc = X + tid;
#pragma unroll 8
            for (int d = 0; d < DD; ++d) {
                float v = xc[d * TILE];
                s = __fadd_rn(s, __fmul_rn(v, v));
            }
            Asm[tid] = s;
            RUNV[tid] = 3.0e38f; RUNI[tid] = 0;
        }
        __syncthreads();

        for (int kb = 0; kb < 8; ++kb) {               // 8 blocks of 128 codes
            const float* cblk = cbl + (size_t)kb * 128 * DD;
            if (tid < 128) E2s[tid] = g_e2[(l * GG + g) * KK + kb * 128 + tid];

            u64t acc[4][4];                            // [token-pair][code]
#pragma unroll
            for (int i = 0; i < 4; ++i)
#pragma unroll
                for (int j = 0; j < 4; ++j) acc[i][j] = 0ull;

#pragma unroll 1
            for (int dc = 0; dc < 16; ++dc) {          // 16 d-chunks of 16
                __syncthreads();                        // E readers of prev chunk done
#pragma unroll
                for (int p = 0; p < 2; ++p) {          // load+transpose 128 codes x 16 d
                    int code = p * 64 + kc;
                    float4 v = *(const float4*)(cblk + (size_t)code * DD + dc * 16 + q * 4);
                    E[(q * 4 + 0) * EPITCH + code] = v.x;
                    E[(q * 4 + 1) * EPITCH + code] = v.y;
                    E[(q * 4 + 2) * EPITCH + code] = v.z;
                    E[(q * 4 + 3) * EPITCH + code] = v.w;
                }
                __syncthreads();
#pragma unroll
                for (int dd = 0; dd < 16; ++dd) {      // sequential d ascending, fused
                    const float* xr = X + (dc * 16 + dd) * TILE + 8 * tm;
                    ulonglong2 a01 = *(const ulonglong2*)xr;        // token pairs, native
                    ulonglong2 a23 = *(const ulonglong2*)(xr + 4);
                    float4 bq = *(const float4*)(E + dd * EPITCH + 4 * tn);
                    u64t ap[4] = {a01.x, a01.y, a23.x, a23.y};
                    u64t bp[4] = {dup2(bq.x), dup2(bq.y), dup2(bq.z), dup2(bq.w)};
#pragma unroll
                    for (int i = 0; i < 4; ++i)
#pragma unroll
                        for (int j = 0; j < 4; ++j)
                            fma2(acc[i][j], ap[i], bp[j]);
                }
            }

            // local argmin: d = fl( fl(a + b_k) - 2c ), ascending code order
#pragma unroll
            for (int i = 0; i < 4; ++i) {
                int tok0 = 8 * tm + 2 * i;
                float alo = Asm[tok0], ahi = Asm[tok0 + 1];
                float blo = 3.0e38f, bhi = 3.0e38f; int ilo = 0, ihi = 0;
#pragma unroll
                for (int j = 0; j < 4; ++j) {
                    float clo, chi;
                    unpack2(acc[i][j], clo, chi);
                    float e2 = E2s[4 * tn + j];
                    float dv = __fadd_rn(__fadd_rn(alo, e2), __fmul_rn(-2.0f, clo));
                    if (dv < blo) { blo = dv; ilo = j; }
                    dv = __fadd_rn(__fadd_rn(ahi, e2), __fmul_rn(-2.0f, chi));
                    if (dv < bhi) { bhi = dv; ihi = j; }
                }
                SCRV[tok0 * 32 + tn] = blo;
                SCRI[tok0 * 32 + tn] = kb * 128 + 4 * tn + ilo;
                SCRV[(tok0 + 1) * 32 + tn] = bhi;
                SCRI[(tok0 + 1) * 32 + tn] = kb * 128 + 4 * tn + ihi;
            }
            __syncthreads();
            if (tid < TILE) {                           // merge, first-index wins
                float bv = RUNV[tid]; int bi = RUNI[tid];
#pragma unroll
                for (int t32 = 0; t32 < 32; ++t32) {    // ascending code order
                    float v = SCRV[tid * 32 + t32];
                    if (v < bv) { bv = v; bi = SCRI[tid * 32 + t32]; }
                }
                RUNV[tid] = bv; RUNI[tid] = bi;
            }
            __syncthreads();
        }

        // indices out
        if (tid < TILE && out_size > IDX_OFF) {
            size_t n = (size_t)b * TT + t0 + tid;
            size_t o = IDX_OFF + ((size_t)(l * GG + g)) * NTOK + n;
            if (o < out_size) dout[o] = (float)RUNI[tid];
        }

        // residual update (reference STE elementwise):
        //   delta = fl(zq - x); quant = fl(x + delta); x' = fl(x - quant)
        {
            int token = tid >> 2, dq = tid & 3;
            int code  = RUNI[token];
            const float* ev = cbl + (size_t)code * DD + dq * 64;
            float* xc = X + (dq * 64) * TILE + token;
#pragma unroll 8
            for (int dd = 0; dd < 64; ++dd) {
                float x  = xc[dd * TILE];
                float dl = __fsub_rn(ev[dd], x);
                float qn = __fadd_rn(x, dl);
                xc[dd * TILE] = __fsub_rn(x, qn);
                lacc += (double)dl * (double)dl;
            }
        }
        __syncthreads();
    }

    // quantized_out = xin - final residual
    for (int i = tid; i < DD * TILE; i += NTH) {
        int d = i >> 6, t = i & 63;
        size_t o = ((size_t)b * (GG * DD) + (size_t)g * DD + d) * TT + t0 + t;
        if (o < out_size && o < QOUT_ELEMS)
            dout[o] = __fsub_rn(xb[(size_t)d * TT + t], X[i]);
    }

    // deterministic per-CTA loss partial
    double* red = (double*)SCRV;
    red[tid] = lacc;
    __syncthreads();
    for (int s = 128; s > 0; s >>= 1) {
        if (tid < s) red[tid] += red[tid + s];
        __syncthreads();
    }
    if (tid == 0) g_loss[blockIdx.y * 1024 + blockIdx.x] = red[0];
}

// ---------------------------------------------------------------- loss reduce
__global__ void loss_kernel(float* __restrict__ dout, unsigned long long out_size) {
    __shared__ double red[256];
    int tid = threadIdx.x;
    double s = 0.0;
    for (int i = tid; i < 2048; i += 256) s += g_loss[i];
    red[tid] = s;
    __syncthreads();
    for (int st = 128; st > 0; st >>= 1) {
        if (tid < st) red[tid] += red[tid + st];
        __syncthreads();
    }
    if (tid == 0 && out_size > LOSS_OFF)
        dout[LOSS_OFF] = (float)(1.25 * red[0] / (8.0 * 33554432.0));
}

// ---------------------------------------------------------------- launch
extern "C" void kernel_launch(void* const* d_in, const int* in_sizes, int n_in,
                              void* d_out, int out_size) {
    const float* xin = (const float*)d_in[0];
    const float* cb  = (const float*)d_in[1];
    if (n_in >= 2 && in_sizes[0] == LL * GG * KK * DD) {
        xin = (const float*)d_in[1];
        cb  = (const float*)d_in[0];
    }
    float* dout = (float*)d_out;
    unsigned long long osz = (unsigned long long)out_size;

    static bool attr_set = false;
    size_t smem = (size_t)(DD * TILE + 16 * EPITCH + 128 + TILE * 32 * 2 + TILE * 3) * 4;
    if (!attr_set) {
        cudaFuncSetAttribute(rvq_kernel, cudaFuncAttributeMaxDynamicSharedMemorySize, (int)smem);
        attr_set = true;
    }

    e2_kernel<<<(LL * GG * KK + 255) / 256, 256>>>(cb);
    dim3 grid(1024, GG);
    rvq_kernel<<<grid, NTH, smem>>>(xin, cb, dout, osz);
    loss_kernel<<<1, 256>>>(dout, osz);
}

// round 6
// speedup vs baseline: 2.0153x; 2.0153x over previous
#include <cuda_runtime.h>
#include <cuda_bf16.h>

// Residual VQ (L=8, G=2, K=1024, D=256), B=16, T=4096, N=65536.
// Strategy: bf16 split MMA (x_hi*e_hi + x_hi*e_lo + x_lo*e_hi, fp32 accum)
// gives approx distances; a sound per-token margin selects <=3 candidates;
// candidates are re-scored with the EXACT reference fp32 semantics
// (sequential d-ascending FMA chain, d = fl(fl(a+b)-2c), first-index argmin).
// STE update / loss / outputs identical to the verified round-3 kernel.

#define LL 8
#define GG 2
#define KK 1024
#define DD 256
#define TT 4096
#define NTOK 65536ull
#define TILE 64
#define NTH 256
#define APITCH 264      // bf16 elements per A row (256 + 8 pad)
#define BPITCH 72       // bf16 elements per B row (64 + 8 pad)

#define QOUT_ELEMS 33554432ull
#define LOSS_OFF   33554432ull
#define IDX_OFF    33554433ull

#define CBELEMS (LL * GG * KK * DD)

__device__ float          g_e2[LL * GG * KK];
__device__ double         g_loss[2048];
__device__ __nv_bfloat16  g_ehi[CBELEMS];
__device__ __nv_bfloat16  g_elo[CBELEMS];

// ---------------------------------------------------------------- helpers
__device__ __forceinline__ void mma16816(float* c, const unsigned* a, const unsigned* b) {
    asm volatile(
        "mma.sync.aligned.m16n8k16.row.col.f32.bf16.bf16.f32 "
        "{%0,%1,%2,%3},{%4,%5,%6,%7},{%8,%9},{%0,%1,%2,%3};"
        : "+f"(c[0]), "+f"(c[1]), "+f"(c[2]), "+f"(c[3])
        : "r"(a[0]), "r"(a[1]), "r"(a[2]), "r"(a[3]), "r"(b[0]), "r"(b[1]));
}

// merge sorted-2 (w1<=w2) into running sorted-2 (v1<=v2)
__device__ __forceinline__ void merge2(float& v1, int& i1, float& v2, int& i2,
                                       float w1, int j1, float w2, int j2) {
    if (w1 < v1) {
        float t2 = v1; int ti2 = i1;
        v1 = w1; i1 = j1;
        if (w2 < t2) { v2 = w2; i2 = j2; } else { v2 = t2; i2 = ti2; }
    } else if (w1 < v2) {
        v2 = w1; i2 = j1;
    }
}

// ---------------------------------------------------------------- ||e||^2 (exact ref rounding)
__global__ void e2_kernel(const float* __restrict__ cb) {
    int c = blockIdx.x * blockDim.x + threadIdx.x;
    if (c >= LL * GG * KK) return;
    const float* e = cb + (size_t)c * DD;
    float s = 0.0f;
    for (int d = 0; d < DD; ++d) {
        float v = e[d];
        s = __fadd_rn(s, __fmul_rn(v, v));
    }
    g_e2[c] = s;
}

// ---------------------------------------------------------------- codebook bf16 split
__global__ void split_e_kernel(const float* __restrict__ cb) {
    int i = blockIdx.x * blockDim.x + threadIdx.x;
    if (i >= CBELEMS) return;
    float v = cb[i];
    __nv_bfloat16 h = __float2bfloat16_rn(v);
    float r = __fsub_rn(v, __bfloat162float(h));
    g_ehi[i] = h;
    g_elo[i] = __float2bfloat16_rn(r);
}

// ---------------------------------------------------------------- main
__global__ void __launch_bounds__(NTH, 1)
rvq_kernel(const float* __restrict__ xin, const float* __restrict__ cb,
           float* __restrict__ dout, unsigned long long out_size) {
    extern __shared__ char smraw[];
    float*          X    = (float*)smraw;                       // [256][64] residual [d][t]
    __nv_bfloat16*  Ah   = (__nv_bfloat16*)(X + DD * TILE);     // [64][APITCH]
    __nv_bfloat16*  Al   = Ah + TILE * APITCH;                  // [64][APITCH]
    __nv_bfloat16*  Bh   = Al + TILE * APITCH;                  // [128][BPITCH]
    __nv_bfloat16*  Bl   = Bh + 128 * BPITCH;                   // [128][BPITCH]
    float*          E2s  = (float*)(Bl + 128 * BPITCH);         // [128]
    float*          Asm  = E2s + 128;                           // [64]
    float*          PV   = Asm + 64;                            // [64][4][2]
    int*            PI   = (int*)(PV + 64 * 8);                 // [64][4][2]
    int*            RUNI = PI + 64 * 8;                         // [64]
    double*         red  = (double*)(RUNI + 64 + 2);            // [256] (8B aligned)

    const int tid  = threadIdx.x;
    const int lane = tid & 31;
    const int warp = tid >> 5;
    const int wm   = warp >> 2;           // 0..1  (32 token rows)
    const int wn   = warp & 3;            // 0..3  (32 code cols)
    const int r4   = lane >> 2;           // 0..7
    const int kq   = lane & 3;            // 0..3

    const int g    = blockIdx.y;
    const int tile = blockIdx.x;
    const int b    = tile >> 6;
    const int t0   = (tile & 63) << 6;
    const float* xb = xin + ((size_t)b * (GG * DD) + (size_t)g * DD) * TT + t0;

    for (int i = tid; i < DD * TILE; i += NTH) {
        int d = i >> 6, t = i & 63;
        X[i] = xb[(size_t)d * TT + t];
    }
    __syncthreads();

    double lacc = 0.0;

    for (int l = 0; l < LL; ++l) {
        const int    cbase = (l * GG + g) * KK;
        const float* cbl   = cb + (size_t)cbase * DD;

        // exact a_n = sequential fl(x^2) sum, d ascending
        if (tid < TILE) {
            float s = 0.0f;
            const float* xc = X + tid;
#pragma unroll 8
            for (int d = 0; d < DD; ++d) {
                float v = xc[d * TILE];
                s = __fadd_rn(s, __fmul_rn(v, v));
            }
            Asm[tid] = s;
        }
        // split residual into A_hi/A_lo bf16 [token][d]
        for (int i = tid; i < DD * TILE; i += NTH) {
            int d = i >> 6, t = i & 63;
            float v = X[d * TILE + t];
            __nv_bfloat16 h = __float2bfloat16_rn(v);
            float rlo = __fsub_rn(v, __bfloat162float(h));
            Ah[t * APITCH + d] = h;
            Al[t * APITCH + d] = __float2bfloat16_rn(rlo);
        }
        __syncthreads();

        // per-token running top-3 (registers of threads tid<64)
        float t3v0 = 3.0e38f, t3v1 = 3.0e38f, t3v2 = 3.0e38f;
        int   t3i0 = 0,       t3i1 = 0,       t3i2 = 0;

        for (int kb = 0; kb < 8; ++kb) {               // 8 blocks of 128 codes
            if (tid < 128) E2s[tid] = g_e2[cbase + kb * 128 + tid];

            float acc[2][4][4];
#pragma unroll
            for (int mt = 0; mt < 2; ++mt)
#pragma unroll
                for (int nt = 0; nt < 4; ++nt)
#pragma unroll
                    for (int e = 0; e < 4; ++e) acc[mt][nt][e] = 0.f;

#pragma unroll 1
            for (int kc = 0; kc < 4; ++kc) {           // 4 d-chunks of 64
                __syncthreads();                        // prev chunk consumed
                // load B chunk: 128 codes x 64 d, both splits
                {
                    const size_t gb = ((size_t)(cbase + kb * 128)) * DD + kc * 64;
#pragma unroll
                    for (int it = 0; it < 4; ++it) {
                        int v = tid + it * NTH;         // 0..1023 16B-vectors
                        int code = v >> 3, dsub = (v & 7) * 8;
                        uint4 hv = *(const uint4*)(g_ehi + gb + (size_t)code * DD + dsub);
                        uint4 lv = *(const uint4*)(g_elo + gb + (size_t)code * DD + dsub);
                        *(uint4*)(Bh + code * BPITCH + dsub) = hv;
                        *(uint4*)(Bl + code * BPITCH + dsub) = lv;
                    }
                }
                __syncthreads();
#pragma unroll
                for (int ks = 0; ks < 4; ++ks) {       // k16 steps
                    const int k0 = kc * 64 + ks * 16 + 2 * kq;
                    unsigned ah[2][4], al[2][4], bh[4][2], bl[4][2];
#pragma unroll
                    for (int mt = 0; mt < 2; ++mt) {
                        int row = wm * 32 + mt * 16 + r4;
                        const unsigned* p0 = (const unsigned*)(Ah + row * APITCH + k0);
                        const unsigned* p1 = (const unsigned*)(Ah + (row + 8) * APITCH + k0);
                        ah[mt][0] = p0[0]; ah[mt][1] = p1[0];
                        ah[mt][2] = p0[4]; ah[mt][3] = p1[4];
                        const unsigned* q0 = (const unsigned*)(Al + row * APITCH + k0);
                        const unsigned* q1 = (const unsigned*)(Al + (row + 8) * APITCH + k0);
                        al[mt][0] = q0[0]; al[mt][1] = q1[0];
                        al[mt][2] = q0[4]; al[mt][3] = q1[4];
                    }
                    const int kl = ks * 16 + 2 * kq;   // local k in chunk
#pragma unroll
                    for (int nt = 0; nt < 4; ++nt) {
                        int col = wn * 32 + nt * 8 + r4;
                        const unsigned* pb = (const unsigned*)(Bh + col * BPITCH + kl);
                        bh[nt][0] = pb[0]; bh[nt][1] = pb[4];
                        const unsigned* ql = (const unsigned*)(Bl + col * BPITCH + kl);
                        bl[nt][0] = ql[0]; bl[nt][1] = ql[4];
                    }
#pragma unroll
                    for (int mt = 0; mt < 2; ++mt)
#pragma unroll
                        for (int nt = 0; nt < 4; ++nt) {
                            mma16816(acc[mt][nt], ah[mt], bh[nt]);
                            mma16816(acc[mt][nt], ah[mt], bl[nt]);
                            mma16816(acc[mt][nt], al[mt], bh[nt]);
                        }
                }
            }

            // epilogue: distances + per-warp per-row top2
#pragma unroll
            for (int mt = 0; mt < 2; ++mt)
#pragma unroll
                for (int h = 0; h < 2; ++h) {
                    int row = wm * 32 + mt * 16 + h * 8 + r4;
                    float a_tok = Asm[row];
                    float v1 = 3.0e38f, v2 = 3.0e38f; int i1 = 0, i2 = 0;
#pragma unroll
                    for (int nt = 0; nt < 4; ++nt)
#pragma unroll
                        for (int j = 0; j < 2; ++j) {
                            int colq = wn * 32 + nt * 8 + 2 * kq + j;
                            float c = acc[mt][nt][h * 2 + j];
                            float dv = __fadd_rn(__fadd_rn(a_tok, E2s[colq]),
                                                 __fmul_rn(-2.0f, c));
                            int idx = kb * 128 + colq;
                            if (dv < v1) { v2 = v1; i2 = i1; v1 = dv; i1 = idx; }
                            else if (dv < v2) { v2 = dv; i2 = idx; }
                        }
#pragma unroll
                    for (int s = 1; s <= 2; s <<= 1) {
                        float w1 = __shfl_xor_sync(0xffffffffu, v1, s);
                        int   j1 = __shfl_xor_sync(0xffffffffu, i1, s);
                        float w2 = __shfl_xor_sync(0xffffffffu, v2, s);
                        int   j2 = __shfl_xor_sync(0xffffffffu, i2, s);
                        merge2(v1, i1, v2, i2, w1, j1, w2, j2);
                    }
                    if (kq == 0) {
                        PV[row * 8 + wn * 2 + 0] = v1;  PI[row * 8 + wn * 2 + 0] = i1;
                        PV[row * 8 + wn * 2 + 1] = v2;  PI[row * 8 + wn * 2 + 1] = i2;
                    }
                }
            __syncthreads();
            if (tid < TILE) {                          // merge 8 partials into top3
#pragma unroll
                for (int e = 0; e < 8; ++e) {
                    float v = PV[tid * 8 + e]; int i = PI[tid * 8 + e];
                    if (v < t3v0) { t3v2 = t3v1; t3i2 = t3i1; t3v1 = t3v0; t3i1 = t3i0;
                                    t3v0 = v; t3i0 = i; }
                    else if (v < t3v1) { t3v2 = t3v1; t3i2 = t3i1; t3v1 = v; t3i1 = i; }
                    else if (v < t3v2) { t3v2 = v; t3i2 = i; }
                }
            }
            __syncthreads();
        }

        // finalize winner: sound margin; exact re-score for ambiguous tokens
        if (tid < TILE) {
            float a_tok  = Asm[tid];
            float margin = __fmaf_rn(a_tok, 2.4e-7f, 1.0e-5f);  // >= 2*(ulp + eps_c)
            int winner = t3i0;
            if (t3v1 <= t3v0 + margin) {
                // collect in-margin candidates, sort ascending index
                int   ci[3]; int nc = 0;
                ci[nc++] = t3i0;
                ci[nc++] = t3i1;
                if (t3v2 <= t3v0 + margin) ci[nc++] = t3i2;
                if (nc == 3) {               // 3-sort by idx
                    int a0 = ci[0], a1 = ci[1], a2 = ci[2], t;
                    if (a1 < a0) { t = a0; a0 = a1; a1 = t; }
                    if (a2 < a1) { t = a1; a1 = a2; a2 = t; }
                    if (a1 < a0) { t = a0; a0 = a1; a1 = t; }
                    ci[0] = a0; ci[1] = a1; ci[2] = a2;
                } else if (ci[1] < ci[0]) { int t = ci[0]; ci[0] = ci[1]; ci[1] = t; }
                float best = 3.0e38f; winner = ci[0];
                for (int cc = 0; cc < nc; ++cc) {
                    int code = ci[cc];
                    const float* ev = cbl + (size_t)code * DD;
                    const float* xc = X + tid;
                    float c = 0.0f;
#pragma unroll 8
                    for (int d = 0; d < DD; ++d)
                        c = __fmaf_rn(xc[d * TILE], ev[d], c);
                    float dv = __fadd_rn(__fadd_rn(a_tok, g_e2[cbase + code]),
                                         __fmul_rn(-2.0f, c));
                    if (dv < best) { best = dv; winner = code; }  // ascending idx scan
                }
            }
            RUNI[tid] = winner;
            if (out_size > IDX_OFF) {
                size_t n = (size_t)b * TT + t0 + tid;
                size_t o = IDX_OFF + ((size_t)(l * GG + g)) * NTOK + n;
                if (o < out_size) dout[o] = (float)winner;
            }
        }
        __syncthreads();

        // residual update (reference STE elementwise)
        {
            int token = tid >> 2, dq = tid & 3;
            int code  = RUNI[token];
            const float* ev = cbl + (size_t)code * DD + dq * 64;
            float* xc = X + (dq * 64) * TILE + token;
#pragma unroll 8
            for (int dd = 0; dd < 64; ++dd) {
                float x  = xc[dd * TILE];
                float dl = __fsub_rn(ev[dd], x);
                float qn = __fadd_rn(x, dl);
                xc[dd * TILE] = __fsub_rn(x, qn);
                lacc += (double)dl * (double)dl;
            }
        }
        __syncthreads();
    }

    // quantized_out = xin - final residual
    for (int i = tid; i < DD * TILE; i += NTH) {
        int d = i >> 6, t = i & 63;
        size_t o = ((size_t)b * (GG * DD) + (size_t)g * DD + d) * TT + t0 + t;
        if (o < out_size && o < QOUT_ELEMS)
            dout[o] = __fsub_rn(xb[(size_t)d * TT + t], X[i]);
    }

    // deterministic per-CTA loss partial
    red[tid] = lacc;
    __syncthreads();
    for (int s = 128; s > 0; s >>= 1) {
        if (tid < s) red[tid] += red[tid + s];
        __syncthreads();
    }
    if (tid == 0) g_loss[blockIdx.y * 1024 + blockIdx.x] = red[0];
}

// ---------------------------------------------------------------- loss reduce
__global__ void loss_kernel(float* __restrict__ dout, unsigned long long out_size) {
    __shared__ double red[256];
    int tid = threadIdx.x;
    double s = 0.0;
    for (int i = tid; i < 2048; i += 256) s += g_loss[i];
    red[tid] = s;
    __syncthreads();
    for (int st = 128; st > 0; st >>= 1) {
        if (tid < st) red[tid] += red[tid + st];
        __syncthreads();
    }
    if (tid == 0 && out_size > LOSS_OFF)
        dout[LOSS_OFF] = (float)(1.25 * red[0] / (8.0 * 33554432.0));
}

// ---------------------------------------------------------------- launch
extern "C" void kernel_launch(void* const* d_in, const int* in_sizes, int n_in,
                              void* d_out, int out_size) {
    const float* xin = (const float*)d_in[0];
    const float* cb  = (const float*)d_in[1];
    if (n_in >= 2 && in_sizes[0] == CBELEMS) {
        xin = (const float*)d_in[1];
        cb  = (const float*)d_in[0];
    }
    float* dout = (float*)d_out;
    unsigned long long osz = (unsigned long long)out_size;

    size_t smem = (size_t)DD * TILE * 4                 // X
                + (size_t)TILE * APITCH * 2 * 2         // Ah, Al
                + (size_t)128 * BPITCH * 2 * 2          // Bh, Bl
                + 128 * 4 + 64 * 4                      // E2s, Asm
                + 64 * 8 * 4 * 2                        // PV, PI
                + (64 + 2) * 4                          // RUNI + align pad
                + 256 * 8;                              // red
    static bool attr_set = false;
    if (!attr_set) {
        cudaFuncSetAttribute(rvq_kernel, cudaFuncAttributeMaxDynamicSharedMemorySize,
                             (int)smem);
        attr_set = true;
    }

    e2_kernel<<<(LL * GG * KK + 255) / 256, 256>>>(cb);
    split_e_kernel<<<(CBELEMS + 255) / 256, 256>>>(cb);
    dim3 grid(1024, GG);
    rvq_kernel<<<grid, NTH, smem>>>(xin, cb, dout, osz);
    loss_kernel<<<1, 256>>>(dout, osz);
}

// round 7
// speedup vs baseline: 2.1259x; 1.0549x over previous
#include <cuda_runtime.h>
#include <cuda_bf16.h>

// Residual VQ (L=8, G=2, K=1024, D=256), B=16, T=4096, N=65536.
// bf16 split MMA (xh*eh + xh*el + xl*eh, fp32 accum) -> approx distances;
// sound margin -> <=3 candidates -> exact fp32 reference-semantics rescore.
// Round 7: cp.async double-buffered B stream + ldmatrix fragment loads.

#define LL 8
#define GG 2
#define KK 1024
#define DD 256
#define TT 4096
#define NTOK 65536ull
#define TILE 64
#define NTH 256
#define APITCH 264      // bf16 per A row (256 + 8 pad)  -> 528B
#define BPITCH 72       // bf16 per B row (64 + 8 pad)   -> 144B

#define QOUT_ELEMS 33554432ull
#define LOSS_OFF   33554432ull
#define IDX_OFF    33554433ull

#define CBELEMS (LL * GG * KK * DD)

// smem byte offsets
#define OFF_X    0
#define OFF_AH   65536
#define OFF_AL   99328
#define OFF_BH0  133120
#define OFF_BL0  151552
#define OFF_BH1  169984
#define OFF_BL1  188416
#define OFF_E2S  206848
#define OFF_ASM  207360
#define OFF_PV   207616
#define OFF_PI   209664
#define OFF_RUNI 211712
#define OFF_RED  211968
#define SMEM_TOT 214016

__device__ float          g_e2[LL * GG * KK];
__device__ double         g_loss[2048];
__device__ __nv_bfloat16  g_ehi[CBELEMS];
__device__ __nv_bfloat16  g_elo[CBELEMS];

// ---------------------------------------------------------------- asm helpers
__device__ __forceinline__ void mma16816(float* c, const unsigned* a, const unsigned* b) {
    asm volatile(
        "mma.sync.aligned.m16n8k16.row.col.f32.bf16.bf16.f32 "
        "{%0,%1,%2,%3},{%4,%5,%6,%7},{%8,%9},{%0,%1,%2,%3};"
        : "+f"(c[0]), "+f"(c[1]), "+f"(c[2]), "+f"(c[3])
        : "r"(a[0]), "r"(a[1]), "r"(a[2]), "r"(a[3]), "r"(b[0]), "r"(b[1]));
}
__device__ __forceinline__ void ldsm_x4(unsigned* r, unsigned addr) {
    asm volatile("ldmatrix.sync.aligned.m8n8.x4.shared.b16 {%0,%1,%2,%3},[%4];"
                 : "=r"(r[0]), "=r"(r[1]), "=r"(r[2]), "=r"(r[3]) : "r"(addr));
}
__device__ __forceinline__ void ldsm_x2(unsigned* r, unsigned addr) {
    asm volatile("ldmatrix.sync.aligned.m8n8.x2.shared.b16 {%0,%1},[%2];"
                 : "=r"(r[0]), "=r"(r[1]) : "r"(addr));
}
__device__ __forceinline__ void cpasync16(unsigned dst, const __nv_bfloat16* src) {
    asm volatile("cp.async.cg.shared.global [%0], [%1], 16;"
                 :: "r"(dst), "l"(__cvta_generic_to_global(src)));
}
__device__ __forceinline__ void merge2(float& v1, int& i1, float& v2, int& i2,
                                       float w1, int j1, float w2, int j2) {
    if (w1 < v1) {
        float t2 = v1; int ti2 = i1;
        v1 = w1; i1 = j1;
        if (w2 < t2) { v2 = w2; i2 = j2; } else { v2 = t2; i2 = ti2; }
    } else if (w1 < v2) {
        v2 = w1; i2 = j1;
    }
}

// ---------------------------------------------------------------- ||e||^2 (exact ref rounding)
__global__ void e2_kernel(const float* __restrict__ cb) {
    int c = blockIdx.x * blockDim.x + threadIdx.x;
    if (c >= LL * GG * KK) return;
    const float* e = cb + (size_t)c * DD;
    float s = 0.0f;
    for (int d = 0; d < DD; ++d) {
        float v = e[d];
        s = __fadd_rn(s, __fmul_rn(v, v));
    }
    g_e2[c] = s;
}

// ---------------------------------------------------------------- codebook bf16 split
__global__ void split_e_kernel(const float* __restrict__ cb) {
    int i = blockIdx.x * blockDim.x + threadIdx.x;
    if (i >= CBELEMS) return;
    float v = cb[i];
    __nv_bfloat16 h = __float2bfloat16_rn(v);
    float r = __fsub_rn(v, __bfloat162float(h));
    g_ehi[i] = h;
    g_elo[i] = __float2bfloat16_rn(r);
}

// ---------------------------------------------------------------- main
__global__ void __launch_bounds__(NTH, 1)
rvq_kernel(const float* __restrict__ xin, const float* __restrict__ cb,
           float* __restrict__ dout, unsigned long long out_size) {
    extern __shared__ char smraw[];
    float*          X    = (float*)(smraw + OFF_X);
    __nv_bfloat16*  Ah   = (__nv_bfloat16*)(smraw + OFF_AH);
    __nv_bfloat16*  Al   = (__nv_bfloat16*)(smraw + OFF_AL);
    float*          E2s  = (float*)(smraw + OFF_E2S);
    float*          Asm  = (float*)(smraw + OFF_ASM);
    float*          PV   = (float*)(smraw + OFF_PV);
    int*            PI   = (int*)(smraw + OFF_PI);
    int*            RUNI = (int*)(smraw + OFF_RUNI);
    double*         red  = (double*)(smraw + OFF_RED);

    const unsigned smbase = (unsigned)__cvta_generic_to_shared(smraw);
    const unsigned uBH[2] = {smbase + OFF_BH0, smbase + OFF_BH1};
    const unsigned uBL[2] = {smbase + OFF_BL0, smbase + OFF_BL1};

    const int tid  = threadIdx.x;
    const int lane = tid & 31;
    const int warp = tid >> 5;
    const int wm   = warp >> 2;           // 0..1  (32 token rows)
    const int wn   = warp & 3;            // 0..3  (32 code cols)
    const int r4   = lane >> 2;           // 0..7
    const int kq   = lane & 3;            // 0..3

    // ldmatrix per-lane address components
    const int lrowA  = (lane & 7) + (((lane >> 3) & 1) << 3);  // row within 16
    const int lkoffA = (lane >> 4) << 3;                        // +0 / +8 k
    const unsigned aBaseH = smbase + OFF_AH +
        (((wm * 32 + lrowA) * APITCH + lkoffA) << 1);
    const unsigned aBaseL = smbase + OFF_AL +
        (((wm * 32 + lrowA) * APITCH + lkoffA) << 1);
    const int rB   = lane & 7;
    const int selB = (lane >> 3) & 1;
    const unsigned bLaneOff = (((wn * 32 + rB) * BPITCH + selB * 8) << 1);

    const int g    = blockIdx.y;
    const int tile = blockIdx.x;
    const int b    = tile >> 6;
    const int t0   = (tile & 63) << 6;
    const float* xb = xin + ((size_t)b * (GG * DD) + (size_t)g * DD) * TT + t0;

    for (int i = tid; i < DD * TILE; i += NTH) {
        int d = i >> 6, t = i & 63;
        X[i] = xb[(size_t)d * TT + t];
    }
    __syncthreads();

    double lacc = 0.0;

    for (int l = 0; l < LL; ++l) {
        const int    cbase = (l * GG + g) * KK;
        const float* cbl   = cb + (size_t)cbase * DD;

        // exact a_n = sequential fl(x^2) sum, d ascending
        if (tid < TILE) {
            float s = 0.0f;
            const float* xc = X + tid;
#pragma unroll 8
            for (int d = 0; d < DD; ++d) {
                float v = xc[d * TILE];
                s = __fadd_rn(s, __fmul_rn(v, v));
            }
            Asm[tid] = s;
        }
        // split residual into A_hi/A_lo bf16 [token][d]
        for (int i = tid; i < DD * TILE; i += NTH) {
            int d = i >> 6, t = i & 63;
            float v = X[d * TILE + t];
            __nv_bfloat16 h = __float2bfloat16_rn(v);
            float rlo = __fsub_rn(v, __bfloat162float(h));
            Ah[t * APITCH + d] = h;
            Al[t * APITCH + d] = __float2bfloat16_rn(rlo);
        }
        __syncthreads();

        float t3v0 = 3.0e38f, t3v1 = 3.0e38f, t3v2 = 3.0e38f;
        int   t3i0 = 0,       t3i1 = 0,       t3i2 = 0;

        for (int kb = 0; kb < 8; ++kb) {               // 8 blocks of 128 codes
            const size_t gbBlk = ((size_t)(cbase + kb * 128)) * DD;
            if (tid < 128) E2s[tid] = g_e2[cbase + kb * 128 + tid];

            // issue chunk 0 into stage 0
            {
                const __nv_bfloat16* sH = g_ehi + gbBlk;
                const __nv_bfloat16* sL = g_elo + gbBlk;
#pragma unroll
                for (int it = 0; it < 4; ++it) {
                    int v = tid + it * NTH;
                    int code = v >> 3, dsub = (v & 7) * 8;
                    unsigned doff = (unsigned)((code * BPITCH + dsub) << 1);
                    cpasync16(uBH[0] + doff, sH + (size_t)code * DD + dsub);
                    cpasync16(uBL[0] + doff, sL + (size_t)code * DD + dsub);
                }
                asm volatile("cp.async.commit_group;");
            }

            float acc[2][4][4];
#pragma unroll
            for (int mt = 0; mt < 2; ++mt)
#pragma unroll
                for (int nt = 0; nt < 4; ++nt)
#pragma unroll
                    for (int e = 0; e < 4; ++e) acc[mt][nt][e] = 0.f;

#pragma unroll 1
            for (int kc = 0; kc < 4; ++kc) {           // 4 d-chunks of 64
                if (kc < 3) {                          // prefetch next chunk
                    const __nv_bfloat16* sH = g_ehi + gbBlk + (kc + 1) * 64;
                    const __nv_bfloat16* sL = g_elo + gbBlk + (kc + 1) * 64;
                    unsigned dh = uBH[(kc + 1) & 1], dl = uBL[(kc + 1) & 1];
#pragma unroll
                    for (int it = 0; it < 4; ++it) {
                        int v = tid + it * NTH;
                        int code = v >> 3, dsub = (v & 7) * 8;
                        unsigned doff = (unsigned)((code * BPITCH + dsub) << 1);
                        cpasync16(dh + doff, sH + (size_t)code * DD + dsub);
                        cpasync16(dl + doff, sL + (size_t)code * DD + dsub);
                    }
                    asm volatile("cp.async.commit_group;");
                    asm volatile("cp.async.wait_group 1;");
                } else {
                    asm volatile("cp.async.wait_group 0;");
                }
                __syncthreads();                        // chunk kc visible to all

                const unsigned bh_st = uBH[kc & 1] + bLaneOff;
                const unsigned bl_st = uBL[kc & 1] + bLaneOff;
#pragma unroll
                for (int ks = 0; ks < 4; ++ks) {       // k16 steps
                    const unsigned akoff = (unsigned)(((kc * 64 + ks * 16)) << 1);
                    const unsigned bkoff = (unsigned)((ks * 16) << 1);
                    unsigned ah[2][4], al[2][4], bh[4][2], bl[4][2];
#pragma unroll
                    for (int mt = 0; mt < 2; ++mt) {
                        ldsm_x4(ah[mt], aBaseH + (unsigned)(mt * 16 * APITCH * 2) + akoff);
                        ldsm_x4(al[mt], aBaseL + (unsigned)(mt * 16 * APITCH * 2) + akoff);
                    }
#pragma unroll
                    for (int nt = 0; nt < 4; ++nt) {
                        ldsm_x2(bh[nt], bh_st + (unsigned)(nt * 8 * BPITCH * 2) + bkoff);
                        ldsm_x2(bl[nt], bl_st + (unsigned)(nt * 8 * BPITCH * 2) + bkoff);
                    }
#pragma unroll
                    for (int mt = 0; mt < 2; ++mt)
#pragma unroll
                        for (int nt = 0; nt < 4; ++nt) {
                            mma16816(acc[mt][nt], ah[mt], bh[nt]);
                            mma16816(acc[mt][nt], ah[mt], bl[nt]);
                            mma16816(acc[mt][nt], al[mt], bh[nt]);
                        }
                }
                __syncthreads();                        // reads done before stage reuse
            }

            // epilogue: distances + per-warp per-row top2
#pragma unroll
            for (int mt = 0; mt < 2; ++mt)
#pragma unroll
                for (int h = 0; h < 2; ++h) {
                    int row = wm * 32 + mt * 16 + h * 8 + r4;
                    float a_tok = Asm[row];
                    float v1 = 3.0e38f, v2 = 3.0e38f; int i1 = 0, i2 = 0;
#pragma unroll
                    for (int nt = 0; nt < 4; ++nt)
#pragma unroll
                        for (int j = 0; j < 2; ++j) {
                            int colq = wn * 32 + nt * 8 + 2 * kq + j;
                            float c = acc[mt][nt][h * 2 + j];
                            float dv = __fadd_rn(__fadd_rn(a_tok, E2s[colq]),
                                                 __fmul_rn(-2.0f, c));
                            int idx = kb * 128 + colq;
                            if (dv < v1) { v2 = v1; i2 = i1; v1 = dv; i1 = idx; }
                            else if (dv < v2) { v2 = dv; i2 = idx; }
                        }
#pragma unroll
                    for (int s = 1; s <= 2; s <<= 1) {
                        float w1 = __shfl_xor_sync(0xffffffffu, v1, s);
                        int   j1 = __shfl_xor_sync(0xffffffffu, i1, s);
                        float w2 = __shfl_xor_sync(0xffffffffu, v2, s);
                        int   j2 = __shfl_xor_sync(0xffffffffu, i2, s);
                        merge2(v1, i1, v2, i2, w1, j1, w2, j2);
                    }
                    if (kq == 0) {
                        PV[row * 8 + wn * 2 + 0] = v1;  PI[row * 8 + wn * 2 + 0] = i1;
                        PV[row * 8 + wn * 2 + 1] = v2;  PI[row * 8 + wn * 2 + 1] = i2;
                    }
                }
            __syncthreads();
            if (tid < TILE) {                          // merge 8 partials into top3
#pragma unroll
                for (int e = 0; e < 8; ++e) {
                    float v = PV[tid * 8 + e]; int i = PI[tid * 8 + e];
                    if (v < t3v0) { t3v2 = t3v1; t3i2 = t3i1; t3v1 = t3v0; t3i1 = t3i0;
                                    t3v0 = v; t3i0 = i; }
                    else if (v < t3v1) { t3v2 = t3v1; t3i2 = t3i1; t3v1 = v; t3i1 = i; }
                    else if (v < t3v2) { t3v2 = v; t3i2 = i; }
                }
            }
            __syncthreads();
        }

        // finalize winner: sound margin; exact re-score for ambiguous tokens
        if (tid < TILE) {
            float a_tok  = Asm[tid];
            float margin = __fmaf_rn(a_tok, 2.4e-7f, 1.0e-5f);
            int winner = t3i0;
            if (t3v1 <= t3v0 + margin) {
                int ci[3]; int nc = 0;
                ci[nc++] = t3i0;
                ci[nc++] = t3i1;
                if (t3v2 <= t3v0 + margin) ci[nc++] = t3i2;
                if (nc == 3) {
                    int a0 = ci[0], a1 = ci[1], a2 = ci[2], t;
                    if (a1 < a0) { t = a0; a0 = a1; a1 = t; }
                    if (a2 < a1) { t = a1; a1 = a2; a2 = t; }
                    if (a1 < a0) { t = a0; a0 = a1; a1 = t; }
                    ci[0] = a0; ci[1] = a1; ci[2] = a2;
                } else if (ci[1] < ci[0]) { int t = ci[0]; ci[0] = ci[1]; ci[1] = t; }
                float best = 3.0e38f; winner = ci[0];
                for (int cc = 0; cc < nc; ++cc) {
                    int code = ci[cc];
                    const float* ev = cbl + (size_t)code * DD;
                    const float* xc = X + tid;
                    float c = 0.0f;
#pragma unroll 8
                    for (int d = 0; d < DD; ++d)
                        c = __fmaf_rn(xc[d * TILE], ev[d], c);
                    float dv = __fadd_rn(__fadd_rn(a_tok, g_e2[cbase + code]),
                                         __fmul_rn(-2.0f, c));
                    if (dv < best) { best = dv; winner = code; }
                }
            }
            RUNI[tid] = winner;
            if (out_size > IDX_OFF) {
                size_t n = (size_t)b * TT + t0 + tid;
                size_t o = IDX_OFF + ((size_t)(l * GG + g)) * NTOK + n;
                if (o < out_size) dout[o] = (float)winner;
            }
        }
        __syncthreads();

        // residual update (reference STE elementwise)
        {
            int token = tid >> 2, dq = tid & 3;
            int code  = RUNI[token];
            const float* ev = cbl + (size_t)code * DD + dq * 64;
            float* xc = X + (dq * 64) * TILE + token;
#pragma unroll 8
            for (int dd = 0; dd < 64; ++dd) {
                float x  = xc[dd * TILE];
                float dl = __fsub_rn(ev[dd], x);
                float qn = __fadd_rn(x, dl);
                xc[dd * TILE] = __fsub_rn(x, qn);
                lacc += (double)dl * (double)dl;
            }
        }
        __syncthreads();
    }

    // quantized_out = xin - final residual
    for (int i = tid; i < DD * TILE; i += NTH) {
        int d = i >> 6, t = i & 63;
        size_t o = ((size_t)b * (GG * DD) + (size_t)g * DD + d) * TT + t0 + t;
        if (o < out_size && o < QOUT_ELEMS)
            dout[o] = __fsub_rn(xb[(size_t)d * TT + t], X[i]);
    }

    // deterministic per-CTA loss partial
    red[tid] = lacc;
    __syncthreads();
    for (int s = 128; s > 0; s >>= 1) {
        if (tid < s) red[tid] += red[tid + s];
        __syncthreads();
    }
    if (tid == 0) g_loss[blockIdx.y * 1024 + blockIdx.x] = red[0];
}

// ---------------------------------------------------------------- loss reduce
__global__ void loss_kernel(float* __restrict__ dout, unsigned long long out_size) {
    __shared__ double red[256];
    int tid = threadIdx.x;
    double s = 0.0;
    for (int i = tid; i < 2048; i += 256) s += g_loss[i];
    red[tid] = s;
    __syncthreads();
    for (int st = 128; st > 0; st >>= 1) {
        if (tid < st) red[tid] += red[tid + st];
        __syncthreads();
    }
    if (tid == 0 && out_size > LOSS_OFF)
        dout[LOSS_OFF] = (float)(1.25 * red[0] / (8.0 * 33554432.0));
}

// ---------------------------------------------------------------- launch
extern "C" void kernel_launch(void* const* d_in, const int* in_sizes, int n_in,
                              void* d_out, int out_size) {
    const float* xin = (const float*)d_in[0];
    const float* cb  = (const float*)d_in[1];
    if (n_in >= 2 && in_sizes[0] == CBELEMS) {
        xin = (const float*)d_in[1];
        cb  = (const float*)d_in[0];
    }
    float* dout = (float*)d_out;
    unsigned long long osz = (unsigned long long)out_size;

    static bool attr_set = false;
    if (!attr_set) {
        cudaFuncSetAttribute(rvq_kernel, cudaFuncAttributeMaxDynamicSharedMemorySize,
                             SMEM_TOT);
        attr_set = true;
    }

    e2_kernel<<<(LL * GG * KK + 255) / 256, 256>>>(cb);
    split_e_kernel<<<(CBELEMS + 255) / 256, 256>>>(cb);
    dim3 grid(1024, GG);
    rvq_kernel<<<grid, NTH, SMEM_TOT>>>(xin, cb, dout, osz);
    loss_kernel<<<1, 256>>>(dout, osz);
}